// round 14
// baseline (speedup 1.0000x reference)
#include <cuda_runtime.h>
#include <cuda_fp16.h>
#include <mma.h>
#include <cstdint>
#include <cstddef>

using namespace nvcuda;

#define NN    8192
#define IND   256
#define HH    128
#define NL    3
#define NNET  3

// ---------------- device scratch (static, allowed) ----------------
__device__ __align__(16) __half g_A16[2][(size_t)NN * NN];       // double-buffered fp16 adj (2x134 MB)
__device__ __align__(16) __half g_X16[NN * IND];
__device__ __align__(16) __half g_Wi16[IND * HH];
__device__ __align__(16) __half g_Ws[NL * 2 * HH * HH];          // fused [Wu_top; Wm@Wu_bot]
__device__ float g_bc[NL * HH];                                   // fused bias
__device__ __align__(16) __half g_h016[NN * HH];
__device__ __align__(16) __half g_comb[NN * 2 * HH];             // [h | msg]
__device__ __align__(16) float g_ps[2 * NN * HH];                // split-K fp32 partials
__device__ float g_invdeg[NNET * NN];                             // per-net 1/deg
__device__ float g_embs[(size_t)NNET * NN * HH];                 // per-net final layer embeddings
__device__ float g_part[128 * HH];

// ---------------- helpers ----------------
__device__ __forceinline__ uint32_t s2u(const void* p){
    uint32_t a;
    asm("{ .reg .u64 t; cvta.to.shared.u64 t, %1; cvt.u32.u64 %0, t; }" : "=r"(a) : "l"(p));
    return a;
}
__device__ __forceinline__ void cp16(uint32_t dst, const void* src){
    asm volatile("cp.async.cg.shared.global [%0], [%1], 16;" :: "r"(dst), "l"(src));
}
#define CP_COMMIT() asm volatile("cp.async.commit_group;" ::: "memory")
#define CP_WAIT2()  asm volatile("cp.async.wait_group 2;" ::: "memory")

// ========== pipelined SpMM, occ-2: part = A16 @ B (fp32 partials) ==========
// grid (128, 2): blockIdx.x = M tile (64 rows), blockIdx.y = K half (4096).
// BM=64, BN=128, BK=64; 4-stage cp.async; 8 warps, warp tile 16x64.
// 26.6 KB/stage * 4 = 106.5 KB -> 2 CTAs/SM (16 warps/SM for latency hiding).
#define GB_S    4
#define GB_ASZ  (64 * 72 * 2)                   //  9216 B
#define GB_BSZ  (64 * 136 * 2)                  // 17408 B
#define GB_STG  (GB_ASZ + GB_BSZ)               // 26624 B
#define GB_SMEM (GB_S * GB_STG)                 // 106496 B

__global__ __launch_bounds__(256, 2) void gemm_big(
    const __half* __restrict__ A,
    const __half* __restrict__ B, int ldb,
    float* __restrict__ part)
{
    extern __shared__ char dsm[];
    uint32_t sb = s2u(dsm);
    int tid = threadIdx.x;
    int wid = tid >> 5;
    int bm = blockIdx.x * 64;
    int kbase = blockIdx.y * 4096;
    int wm = (wid >> 1) * 16;
    int wn = (wid & 1) * 64;

    auto load_stage = [&](int st, int kt) {
        int k0 = kbase + kt * 64;
        uint32_t abase = sb + st * GB_STG;
        uint32_t bbase = abase + GB_ASZ;
#pragma unroll
        for (int i = 0; i < 2; i++) {           // A: 64 x 64 halves
            int idx = tid + i * 256;
            int r = idx >> 3, c = idx & 7;
            cp16(abase + r * 144 + c * 16,
                 A + (size_t)(bm + r) * NN + k0 + c * 8);
        }
#pragma unroll
        for (int i = 0; i < 4; i++) {           // B: 64 x 128 halves
            int idx = tid + i * 256;
            int r = idx >> 4, c = idx & 15;
            cp16(bbase + r * 272 + c * 16,
                 B + (size_t)(k0 + r) * ldb + c * 8);
        }
    };

    wmma::fragment<wmma::accumulator, 16, 16, 16, float> acc[4];
#pragma unroll
    for (int j = 0; j < 4; j++) wmma::fill_fragment(acc[j], 0.0f);

#pragma unroll
    for (int s = 0; s < GB_S - 1; s++) { load_stage(s, s); CP_COMMIT(); }

    const int nk = 4096 / 64;
    int st_use = 0, st_load = GB_S - 1;
    for (int kt = 0; kt < nk; kt++) {
        CP_WAIT2();
        __syncthreads();
        if (kt + GB_S - 1 < nk) load_stage(st_load, kt + GB_S - 1);
        CP_COMMIT();

        const __half* pA = reinterpret_cast<const __half*>(dsm + st_use * GB_STG);
        const __half* pB = reinterpret_cast<const __half*>(dsm + st_use * GB_STG + GB_ASZ);
#pragma unroll
        for (int kk = 0; kk < 64; kk += 16) {
            wmma::fragment<wmma::matrix_a, 16, 16, 16, __half, wmma::row_major> fa;
            wmma::fragment<wmma::matrix_b, 16, 16, 16, __half, wmma::row_major> fb[4];
            wmma::load_matrix_sync(fa, pA + (size_t)wm * 72 + kk, 72);
#pragma unroll
            for (int j = 0; j < 4; j++)
                wmma::load_matrix_sync(fb[j], pB + (size_t)kk * 136 + wn + 16 * j, 136);
#pragma unroll
            for (int j = 0; j < 4; j++)
                wmma::mma_sync(acc[j], fa, fb[j], acc[j]);
        }
        __syncthreads();
        if (++st_use == GB_S) st_use = 0;
        if (++st_load == GB_S) st_load = 0;
    }

    float* sC = reinterpret_cast<float*>(dsm);     // 64 x 132
#pragma unroll
    for (int j = 0; j < 4; j++)
        wmma::store_matrix_sync(sC + (size_t)wm * 132 + wn + 16 * j,
                                acc[j], 132, wmma::mem_row_major);
    __syncthreads();

    float* out = part + (size_t)blockIdx.y * NN * HH + (size_t)bm * HH;
    for (int e = tid; e < 64 * 128 / 4; e += 256) {
        int r = e >> 5, c = (e & 31) * 4;
        *reinterpret_cast<float4*>(out + (size_t)r * HH + c) =
            *reinterpret_cast<const float4*>(sC + (size_t)r * 132 + c);
    }
}

// ---------------- adj fp32 -> fp16 + row-sum (one pass, pure-BW) ----------------
__global__ void prep_adj(const float* __restrict__ src0,
                         __half* __restrict__ dst0,
                         float* __restrict__ invdeg)
{
    size_t row = blockIdx.x;                 // 0..NN-1
    const float* src = src0 + row * NN;
    __half* dst = dst0 + row * NN;
    int t = threadIdx.x;                     // 256
    float s = 0.f;
#pragma unroll
    for (int i = 0; i < 8; i++) {
        int v4 = t + i * 256;
        float4 f = *reinterpret_cast<const float4*>(src + (size_t)v4 * 4);
        s += f.x + f.y + f.z + f.w;
        __half2 h0 = __floats2half2_rn(f.x, f.y);
        __half2 h1 = __floats2half2_rn(f.z, f.w);
        uint2 u;
        u.x = *reinterpret_cast<unsigned*>(&h0);
        u.y = *reinterpret_cast<unsigned*>(&h1);
        *reinterpret_cast<uint2*>(dst + (size_t)v4 * 4) = u;
    }
#pragma unroll
    for (int o = 16; o; o >>= 1) s += __shfl_xor_sync(0xFFFFFFFFu, s, o);
    __shared__ float ws[8];
    int wid = t >> 5, lane = t & 31;
    if (lane == 0) ws[wid] = s;
    __syncthreads();
    if (t == 0) {
        float tot = 0.f;
#pragma unroll
        for (int i = 0; i < 8; i++) tot += ws[i];
        invdeg[row] = 1.0f / fmaxf(tot, 1.0f);
    }
}

// ---- combine split-K partials: comb[:,128:256] = (p0+p1)*invdeg (fp16) ----
__global__ void combine_k(const float* __restrict__ inv)
{
    int i = blockIdx.x * 256 + threadIdx.x;       // float4 group
    int n = i >> 5, coff = (i & 31) * 4;
    float s = inv[n];
    const float4* p = reinterpret_cast<const float4*>(g_ps);
    float4 a = p[i], b = p[i + NN * HH / 4];
    __half2 h0 = __floats2half2_rn((a.x + b.x) * s, (a.y + b.y) * s);
    __half2 h1 = __floats2half2_rn((a.z + b.z) * s, (a.w + b.w) * s);
    uint2 u;
    u.x = *reinterpret_cast<unsigned*>(&h0);
    u.y = *reinterpret_cast<unsigned*>(&h1);
    *reinterpret_cast<uint2*>(g_comb + (size_t)n * 256 + 128 + coff) = u;
}

// ---------------- generic fp32 -> fp16 convert ----------------
__global__ void f2h(const float* __restrict__ src, __half* __restrict__ dst, int n4)
{
    int i = blockIdx.x * blockDim.x + threadIdx.x;
    if (i < n4) {
        float4 f = reinterpret_cast<const float4*>(src)[i];
        __half2 a = __floats2half2_rn(f.x, f.y);
        __half2 b = __floats2half2_rn(f.z, f.w);
        uint2 u;
        u.x = *reinterpret_cast<unsigned*>(&a);
        u.y = *reinterpret_cast<unsigned*>(&b);
        *reinterpret_cast<uint2*>(dst + (size_t)i * 4) = u;
    }
}

// ------- fused weight precompute: Ws[l] = [Wu_top ; Wm[l]@Wu_bot], bc[l] = bm@Wu_bot + bu -------
__global__ void fuse_w(const float* __restrict__ Wm, const float* __restrict__ Wu,
                       const float* __restrict__ bm, const float* __restrict__ bu)
{
    int l = blockIdx.y;
    int r = blockIdx.x;          // 0..256
    int j = threadIdx.x;         // 128
    const float* WuL = Wu + (size_t)l * 2 * HH * HH;   // [256][128]
    if (r < HH) {
        g_Ws[((size_t)l * 256 + r) * HH + j] = __float2half(WuL[(size_t)r * HH + j]);
    } else if (r < 2 * HH) {
        int rr = r - HH;
        __shared__ float wm[HH];
        wm[j] = Wm[((size_t)l * HH + rr) * HH + j];
        __syncthreads();
        float acc = 0.f;
#pragma unroll 8
        for (int k = 0; k < HH; k++)
            acc += wm[k] * WuL[(size_t)(HH + k) * HH + j];
        g_Ws[((size_t)l * 256 + r) * HH + j] = __float2half(acc);
    } else {
        __shared__ float bb[HH];
        bb[j] = bm[l * HH + j];
        __syncthreads();
        float acc = bu[l * HH + j];
#pragma unroll 8
        for (int k = 0; k < HH; k++)
            acc += bb[k] * WuL[(size_t)(HH + k) * HH + j];
        g_bc[l * HH + j] = acc;
    }
}

// ---------------- comb[:,0:128] = h0_16 ----------------
__global__ void copy_h0()
{
    int i = blockIdx.x * 256 + threadIdx.x;
    if (i < NN * HH / 8) {
        int n = i >> 4;
        int c = (i & 15) * 8;
        *reinterpret_cast<float4*>(g_comb + (size_t)n * 256 + c) =
            *reinterpret_cast<const float4*>(g_h016 + (size_t)n * 128 + c);
    }
}

// -------- fp16 wmma GEMM, BM=32 (grid 256 -> good occupancy for small-K GEMMs) --------
__global__ __launch_bounds__(256) void gemm_k(
    const __half* __restrict__ A, int lda,
    const __half* __restrict__ B, int ldb,
    float* __restrict__ C32, int ldc32,
    __half* __restrict__ C16, int ldc16,
    const float* __restrict__ bias,
    int K, int relu)
{
    constexpr int BM = 32, BN = 128, BK = 64;
    __shared__ __align__(16) char sraw[22016];    // sA 32x72x2=4608, sB 64x136x2=17408
    __half (*sA)[BK + 8] = reinterpret_cast<__half(*)[BK + 8]>(sraw);
    __half (*sB)[BN + 8] = reinterpret_cast<__half(*)[BN + 8]>(sraw + 4608);
    float* sC = reinterpret_cast<float*>(sraw);   // 32x132 f32 = 16896 B

    int tid = threadIdx.x;
    int wid = tid >> 5;
    int bm = blockIdx.x * BM;
    int wm = (wid >> 2) * 16;
    int wn = (wid & 3) * 32;

    wmma::fragment<wmma::accumulator, 16, 16, 16, float> acc[2];
#pragma unroll
    for (int j = 0; j < 2; j++) wmma::fill_fragment(acc[j], 0.0f);

    float4 ra, rb[4];
    {
        int idx = tid * 8;
        ra = *reinterpret_cast<const float4*>(A + (size_t)(bm + (idx >> 6)) * lda + (idx & 63));
#pragma unroll
        for (int i = 0; i < 4; i++) {
            int bidx = tid * 8 + i * 2048;
            rb[i] = *reinterpret_cast<const float4*>(B + (size_t)(bidx >> 7) * ldb + (bidx & 127));
        }
    }

    int nk = K >> 6;
    for (int kt = 0; kt < nk; kt++) {
        {
            int idx = tid * 8;
            *reinterpret_cast<float4*>(&sA[idx >> 6][idx & 63]) = ra;
#pragma unroll
            for (int i = 0; i < 4; i++) {
                int bidx = tid * 8 + i * 2048;
                *reinterpret_cast<float4*>(&sB[bidx >> 7][bidx & 127]) = rb[i];
            }
        }
        __syncthreads();

        if (kt + 1 < nk) {
            int k0 = (kt + 1) << 6;
            int idx = tid * 8;
            ra = *reinterpret_cast<const float4*>(A + (size_t)(bm + (idx >> 6)) * lda + k0 + (idx & 63));
#pragma unroll
            for (int i = 0; i < 4; i++) {
                int bidx = tid * 8 + i * 2048;
                rb[i] = *reinterpret_cast<const float4*>(B + (size_t)(k0 + (bidx >> 7)) * ldb + (bidx & 127));
            }
        }

#pragma unroll
        for (int kk = 0; kk < BK; kk += 16) {
            wmma::fragment<wmma::matrix_a, 16, 16, 16, __half, wmma::row_major> fa;
            wmma::fragment<wmma::matrix_b, 16, 16, 16, __half, wmma::row_major> fb[2];
            wmma::load_matrix_sync(fa, &sA[wm][kk], BK + 8);
            wmma::load_matrix_sync(fb[0], &sB[kk][wn], BN + 8);
            wmma::load_matrix_sync(fb[1], &sB[kk][wn + 16], BN + 8);
#pragma unroll
            for (int j = 0; j < 2; j++)
                wmma::mma_sync(acc[j], fa, fb[j], acc[j]);
        }
        __syncthreads();
    }

#pragma unroll
    for (int j = 0; j < 2; j++)
        wmma::store_matrix_sync(sC + (size_t)wm * 132 + (wn + 16 * j),
                                acc[j], 132, wmma::mem_row_major);
    __syncthreads();

    for (int e = tid; e < BM * BN; e += 256) {
        int r = e >> 7, c = e & 127;
        float vv = sC[r * 132 + c];
        if (bias) vv += bias[c];
        if (relu) vv = fmaxf(vv, 0.0f);
        if (C16) C16[(size_t)(bm + r) * ldc16 + c] = __float2half(vv);
        if (C32) C32[(size_t)(bm + r) * ldc32 + c] = vv;
    }
}

// ---------------- attention over layers + output projection ----------------
__global__ __launch_bounds__(256) void attn_out(
    const float* __restrict__ Wa, const float* __restrict__ ba,
    const float* __restrict__ v, const float* __restrict__ Wo,
    const float* __restrict__ bo, float* __restrict__ out)
{
    __shared__ float sWa[HH * 4];
    __shared__ float sba[4], sv[4];
    __shared__ float smix[8][4][132];
    int t = threadIdx.x;
    for (int i = t; i < HH * 4; i += 256) sWa[i] = Wa[i];
    if (t < 4) { sba[t] = ba[t]; sv[t] = v[t]; }
    __syncthreads();

    int w = t >> 5, lane = t & 31;
    for (int q = 0; q < 4; q++) {
        int n = blockIdx.x * 32 + w * 4 + q;
        float e[3][4];
#pragma unroll
        for (int l = 0; l < 3; l++)
#pragma unroll
            for (int ii = 0; ii < 4; ii++)
                e[l][ii] = g_embs[((size_t)l * NN + n) * HH + lane + 32 * ii];

        float sc[3];
#pragma unroll
        for (int l = 0; l < 3; l++) {
            float s = 0.f;
#pragma unroll
            for (int hd = 0; hd < 4; hd++) {
                float d = 0.f;
#pragma unroll
                for (int ii = 0; ii < 4; ii++)
                    d += e[l][ii] * sWa[(lane + 32 * ii) * 4 + hd];
#pragma unroll
                for (int o = 16; o; o >>= 1) d += __shfl_xor_sync(0xFFFFFFFFu, d, o);
                s += tanhf(d + sba[hd]) * sv[hd];
            }
            sc[l] = s;
        }
        float mx = fmaxf(sc[0], fmaxf(sc[1], sc[2]));
        float w0 = expf(sc[0] - mx), w1 = expf(sc[1] - mx), w2 = expf(sc[2] - mx);
        float inv = 1.0f / (w0 + w1 + w2);
        w0 *= inv; w1 *= inv; w2 *= inv;
#pragma unroll
        for (int ii = 0; ii < 4; ii++)
            smix[w][q][lane + 32 * ii] = w0 * e[0][ii] + w1 * e[1][ii] + w2 * e[2][ii];
        __syncwarp();
#pragma unroll
        for (int jj = 0; jj < 4; jj++) {
            int j = lane + 32 * jj;
            float a = bo[j];
            for (int h = 0; h < HH; h++)
                a += smix[w][q][h] * Wo[h * HH + j];
            out[(size_t)n * HH + j] = a;
        }
        __syncwarp();
    }
}

// ---------------- deterministic mean reduction ----------------
__global__ void mean_part(const float* __restrict__ out)
{
    int b = blockIdx.x;
    int t = threadIdx.x;
    float s = 0.f;
    for (int r = 0; r < 64; r++)
        s += out[((size_t)b * 64 + r) * HH + t];
    g_part[b * HH + t] = s;
}
__global__ void mean_fin(float* __restrict__ gout)
{
    int t = threadIdx.x;
    float s = 0.f;
    for (int i = 0; i < 128; i++) s += g_part[i * HH + t];
    gout[t] = s * (1.0f / (float)NN);
}

// ---------------- launcher ----------------
extern "C" void kernel_launch(void* const* d_in, const int* in_sizes, int n_in,
                              void* d_out, int out_size)
{
    (void)in_sizes; (void)n_in; (void)out_size;
    const float* nf  = (const float*)d_in[0];
    const float* adj = (const float*)d_in[1];
    const float* bi  = (const float*)d_in[3];
    const float* Wa  = (const float*)d_in[8];
    const float* ba  = (const float*)d_in[9];
    const float* v   = (const float*)d_in[10];
    const float* Wo  = (const float*)d_in[11];
    const float* bo  = (const float*)d_in[12];
    float* out = (float*)d_out;

    __half *A16, *X16, *Wi16, *Ws, *h016, *comb;
    float *invdeg, *embs, *ps, *bc;
    cudaGetSymbolAddress((void**)&A16,   g_A16);
    cudaGetSymbolAddress((void**)&X16,   g_X16);
    cudaGetSymbolAddress((void**)&Wi16,  g_Wi16);
    cudaGetSymbolAddress((void**)&Ws,    g_Ws);
    cudaGetSymbolAddress((void**)&h016,  g_h016);
    cudaGetSymbolAddress((void**)&comb,  g_comb);
    cudaGetSymbolAddress((void**)&invdeg, g_invdeg);
    cudaGetSymbolAddress((void**)&embs,  g_embs);
    cudaGetSymbolAddress((void**)&ps,    g_ps);
    cudaGetSymbolAddress((void**)&bc,    g_bc);

    cudaFuncSetAttribute(gemm_big, cudaFuncAttributeMaxDynamicSharedMemorySize, GB_SMEM);

    // side stream + events for overlapping prep_adj(net+1) with net-k compute.
    cudaStream_t s = 0;
    if (cudaStreamCreateWithFlags(&s, cudaStreamNonBlocking) != cudaSuccess) s = 0;
    cudaEvent_t e0, eF[2], eP[3];
    cudaEventCreateWithFlags(&e0, cudaEventDisableTiming);
    for (int i = 0; i < 2; i++) cudaEventCreateWithFlags(&eF[i], cudaEventDisableTiming);
    for (int i = 0; i < 3; i++) cudaEventCreateWithFlags(&eP[i], cudaEventDisableTiming);

    // fork: prep net 0 into buffer 0 on side stream
    cudaEventRecord(e0, 0);
    cudaStreamWaitEvent(s, e0, 0);
    prep_adj<<<NN, 256, 0, s>>>(adj, A16, invdeg);
    cudaEventRecord(eP[0], s);

    // main: minimal prep before first SpMM (also positions gemm_big early for ncu window)
    f2h<<<(NN * IND / 4 + 255) / 256, 256>>>(nf, X16, NN * IND / 4);
    f2h<<<(IND * HH / 4 + 255) / 256, 256>>>((const float*)d_in[2], Wi16, IND * HH / 4);
    gemm_k<<<256, 256>>>(X16, IND, Wi16, HH,
                         nullptr, 0, h016, HH, bi, IND, 0);

    bool fused = false;
    // message passing; prep of net+1 overlaps net's compute chain (disjoint A16 buffer)
    for (int net = 0; net < NNET; net++) {
        int buf = net & 1;
        cudaStreamWaitEvent(0, eP[net], 0);          // A16[buf] ready
        if (net + 1 < NNET) {
            cudaEventRecord(eF[net & 1], 0);         // main done reading A16[buf^1]
            cudaStreamWaitEvent(s, eF[net & 1], 0);
            prep_adj<<<NN, 256, 0, s>>>(adj + (size_t)(net + 1) * NN * NN,
                                        A16 + (size_t)((net + 1) & 1) * NN * NN,
                                        invdeg + (net + 1) * NN);
            cudaEventRecord(eP[net + 1], s);
        }
        for (int l = 0; l < NL; l++) {
            const __half* Bsrc = (l == 0) ? h016 : comb;
            int ldb = (l == 0) ? HH : 2 * HH;
            gemm_big<<<dim3(NN / 64, 2), 256, GB_SMEM>>>(
                A16 + (size_t)buf * NN * NN, Bsrc, ldb, ps);
            if (l == 0) {
                copy_h0<<<(NN * HH / 8 + 255) / 256, 256>>>();
                if (!fused) {
                    fuse_w<<<dim3(2 * HH + 1, NL), HH>>>(
                        (const float*)d_in[4], (const float*)d_in[6],
                        (const float*)d_in[5], (const float*)d_in[7]);
                    fused = true;
                }
            }
            combine_k<<<NN * HH / 4 / 256, 256>>>(invdeg + net * NN);
            float* c32 = (l == NL - 1) ? (embs + (size_t)net * NN * HH) : nullptr;
            gemm_k<<<256, 256>>>(comb, 2 * HH, Ws + (size_t)l * 2 * HH * HH, HH,
                                 c32, HH, comb, 2 * HH,
                                 bc + l * HH, 2 * HH, 1);
        }
    }

    // cross-layer attention + output projection
    attn_out<<<NN / 32, 256>>>(Wa, ba, v, Wo, bo, out);

    // deterministic mean over nodes
    mean_part<<<128, 128>>>(out);
    mean_fin<<<1, 128>>>(out + (size_t)NN * HH);
}

// round 15
// speedup vs baseline: 1.0614x; 1.0614x over previous
#include <cuda_runtime.h>
#include <cuda_fp16.h>
#include <mma.h>
#include <cstdint>
#include <cstddef>

using namespace nvcuda;

#define NN    8192
#define IND   256
#define HH    128
#define NL    3
#define NNET  3

// ---------------- device scratch (static, allowed) ----------------
__device__ __align__(16) __half g_A16[2][(size_t)NN * NN];       // double-buffered fp16 adj (2x134 MB)
__device__ __align__(16) __half g_X16[NN * IND];
__device__ __align__(16) __half g_Wi16[IND * HH];
__device__ __align__(16) __half g_Ws[NL * 2 * HH * HH];          // fused [Wu_top; Wm@Wu_bot]
__device__ float g_bc[NL * HH];                                   // fused bias
__device__ __align__(16) __half g_h016[NN * HH];
__device__ __align__(16) __half g_comb[NN * 2 * HH];             // [h | msg]
__device__ __align__(16) float g_ps[2 * NN * HH];                // split-K fp32 partials
__device__ float g_invdeg[NNET * NN];                             // per-net 1/deg
__device__ float g_embs[(size_t)NNET * NN * HH];                 // per-net final layer embeddings
__device__ float g_part[128 * HH];

// ---------------- helpers ----------------
__device__ __forceinline__ uint32_t s2u(const void* p){
    uint32_t a;
    asm("{ .reg .u64 t; cvta.to.shared.u64 t, %1; cvt.u32.u64 %0, t; }" : "=r"(a) : "l"(p));
    return a;
}
__device__ __forceinline__ void cp16(uint32_t dst, const void* src){
    asm volatile("cp.async.cg.shared.global [%0], [%1], 16;" :: "r"(dst), "l"(src));
}
#define CP_COMMIT() asm volatile("cp.async.commit_group;" ::: "memory")
#define CP_WAIT2()  asm volatile("cp.async.wait_group 2;" ::: "memory")

// =================== pipelined SpMM: part = A16 @ B (fp32 partials) ===================
// grid (64, 2). BM=128, BK=64, 6 stages, occ-1 (round-13 measured-best shape),
// restructured: TWO stages consumed per barrier -> 32 syncs instead of 128.
#define GB_S    6
#define GB_ASZ  (128 * 72 * 2)                  // 18432 B
#define GB_BSZ  (64 * 136 * 2)                  // 17408 B
#define GB_STG  (GB_ASZ + GB_BSZ)               // 35840 B
#define GB_SMEM (GB_S * GB_STG)                 // 215040 B

__global__ __launch_bounds__(256, 1) void gemm_big(
    const __half* __restrict__ A,
    const __half* __restrict__ B, int ldb,
    float* __restrict__ part)
{
    extern __shared__ char dsm[];
    uint32_t sb = s2u(dsm);
    int tid = threadIdx.x;
    int wid = tid >> 5;
    int bm = blockIdx.x * 128;
    int kbase = blockIdx.y * 4096;
    int wm = (wid >> 1) * 32;
    int wn = (wid & 1) * 64;

    auto load_stage = [&](int st, int kt) {
        int k0 = kbase + kt * 64;
        uint32_t abase = sb + st * GB_STG;
        uint32_t bbase = abase + GB_ASZ;
#pragma unroll
        for (int i = 0; i < 4; i++) {
            int idx = tid + i * 256;
            int r = idx >> 3, c = idx & 7;
            cp16(abase + r * 144 + c * 16,
                 A + (size_t)(bm + r) * NN + k0 + c * 8);
        }
#pragma unroll
        for (int i = 0; i < 4; i++) {
            int idx = tid + i * 256;
            int r = idx >> 4, c = idx & 15;
            cp16(bbase + r * 272 + c * 16,
                 B + (size_t)(k0 + r) * ldb + c * 8);
        }
    };

    // one 64-K stage's worth of MMA for this warp
    auto mma_stage = [&](int st,
                         wmma::fragment<wmma::accumulator, 16, 16, 16, float> (&acc)[2][4]) {
        const __half* pA = reinterpret_cast<const __half*>(dsm + st * GB_STG);
        const __half* pB = reinterpret_cast<const __half*>(dsm + st * GB_STG + GB_ASZ);
#pragma unroll
        for (int kk = 0; kk < 64; kk += 16) {
            wmma::fragment<wmma::matrix_a, 16, 16, 16, __half, wmma::row_major> fa[2];
            wmma::fragment<wmma::matrix_b, 16, 16, 16, __half, wmma::row_major> fb[4];
#pragma unroll
            for (int i = 0; i < 2; i++)
                wmma::load_matrix_sync(fa[i], pA + (size_t)(wm + 16 * i) * 72 + kk, 72);
#pragma unroll
            for (int j = 0; j < 4; j++)
                wmma::load_matrix_sync(fb[j], pB + (size_t)kk * 136 + wn + 16 * j, 136);
#pragma unroll
            for (int i = 0; i < 2; i++)
#pragma unroll
                for (int j = 0; j < 4; j++)
                    wmma::mma_sync(acc[i][j], fa[i], fb[j], acc[i][j]);
        }
    };

    wmma::fragment<wmma::accumulator, 16, 16, 16, float> acc[2][4];
#pragma unroll
    for (int i = 0; i < 2; i++)
#pragma unroll
        for (int j = 0; j < 4; j++)
            wmma::fill_fragment(acc[i][j], 0.0f);

    // prologue: 4 stages in flight (one commit group each)
#pragma unroll
    for (int s = 0; s < 4; s++) { load_stage(s, s); CP_COMMIT(); }

    const int nk = 4096 / 64;                    // 64 stages total
    int st_use = 0, st_load = 4;
    for (int kt = 0; kt < nk; kt += 2) {
        // allow 2 newest groups pending -> stages kt, kt+1 are complete.
        // commits below are unconditional, so group counting stays exact in the tail
        // (empty groups complete immediately).
        CP_WAIT2();
        __syncthreads();                         // all warps done reading stages kt-2, kt-1

        if (kt + 4 < nk) load_stage(st_load, kt + 4);
        CP_COMMIT();
        int st_load2 = (st_load + 1 == GB_S) ? 0 : st_load + 1;
        if (kt + 5 < nk) load_stage(st_load2, kt + 5);
        CP_COMMIT();

        mma_stage(st_use, acc);
        int st_use2 = (st_use + 1 == GB_S) ? 0 : st_use + 1;
        mma_stage(st_use2, acc);

        st_use = (st_use + 2 >= GB_S) ? st_use + 2 - GB_S : st_use + 2;
        st_load = (st_load + 2 >= GB_S) ? st_load + 2 - GB_S : st_load + 2;
    }

    __syncthreads();                             // all warps done with last MMA reads
    float* sC = reinterpret_cast<float*>(dsm);   // 128 x 132 overlays stage memory
#pragma unroll
    for (int i = 0; i < 2; i++)
#pragma unroll
        for (int j = 0; j < 4; j++)
            wmma::store_matrix_sync(sC + (size_t)(wm + 16 * i) * 132 + wn + 16 * j,
                                    acc[i][j], 132, wmma::mem_row_major);
    __syncthreads();

    float* out = part + (size_t)blockIdx.y * NN * HH + (size_t)bm * HH;
    for (int e = tid; e < 128 * 128 / 4; e += 256) {
        int r = e >> 5, c = (e & 31) * 4;
        *reinterpret_cast<float4*>(out + (size_t)r * HH + c) =
            *reinterpret_cast<const float4*>(sC + (size_t)r * 132 + c);
    }
}

// ---------------- adj fp32 -> fp16 + row-sum (one pass, pure-BW) ----------------
__global__ void prep_adj(const float* __restrict__ src0,
                         __half* __restrict__ dst0,
                         float* __restrict__ invdeg)
{
    size_t row = blockIdx.x;                 // 0..NN-1
    const float* src = src0 + row * NN;
    __half* dst = dst0 + row * NN;
    int t = threadIdx.x;                     // 256
    float s = 0.f;
#pragma unroll
    for (int i = 0; i < 8; i++) {
        int v4 = t + i * 256;
        float4 f = *reinterpret_cast<const float4*>(src + (size_t)v4 * 4);
        s += f.x + f.y + f.z + f.w;
        __half2 h0 = __floats2half2_rn(f.x, f.y);
        __half2 h1 = __floats2half2_rn(f.z, f.w);
        uint2 u;
        u.x = *reinterpret_cast<unsigned*>(&h0);
        u.y = *reinterpret_cast<unsigned*>(&h1);
        *reinterpret_cast<uint2*>(dst + (size_t)v4 * 4) = u;
    }
#pragma unroll
    for (int o = 16; o; o >>= 1) s += __shfl_xor_sync(0xFFFFFFFFu, s, o);
    __shared__ float ws[8];
    int wid = t >> 5, lane = t & 31;
    if (lane == 0) ws[wid] = s;
    __syncthreads();
    if (t == 0) {
        float tot = 0.f;
#pragma unroll
        for (int i = 0; i < 8; i++) tot += ws[i];
        invdeg[row] = 1.0f / fmaxf(tot, 1.0f);
    }
}

// ---- combine split-K partials: comb[:,128:256] = (p0+p1)*invdeg (fp16) ----
__global__ void combine_k(const float* __restrict__ inv)
{
    int i = blockIdx.x * 256 + threadIdx.x;       // float4 group
    int n = i >> 5, coff = (i & 31) * 4;
    float s = inv[n];
    const float4* p = reinterpret_cast<const float4*>(g_ps);
    float4 a = p[i], b = p[i + NN * HH / 4];
    __half2 h0 = __floats2half2_rn((a.x + b.x) * s, (a.y + b.y) * s);
    __half2 h1 = __floats2half2_rn((a.z + b.z) * s, (a.w + b.w) * s);
    uint2 u;
    u.x = *reinterpret_cast<unsigned*>(&h0);
    u.y = *reinterpret_cast<unsigned*>(&h1);
    *reinterpret_cast<uint2*>(g_comb + (size_t)n * 256 + 128 + coff) = u;
}

// ---------------- generic fp32 -> fp16 convert ----------------
__global__ void f2h(const float* __restrict__ src, __half* __restrict__ dst, int n4)
{
    int i = blockIdx.x * blockDim.x + threadIdx.x;
    if (i < n4) {
        float4 f = reinterpret_cast<const float4*>(src)[i];
        __half2 a = __floats2half2_rn(f.x, f.y);
        __half2 b = __floats2half2_rn(f.z, f.w);
        uint2 u;
        u.x = *reinterpret_cast<unsigned*>(&a);
        u.y = *reinterpret_cast<unsigned*>(&b);
        *reinterpret_cast<uint2*>(dst + (size_t)i * 4) = u;
    }
}

// ------- fused weight precompute: Ws[l] = [Wu_top ; Wm[l]@Wu_bot], bc[l] = bm@Wu_bot + bu -------
__global__ void fuse_w(const float* __restrict__ Wm, const float* __restrict__ Wu,
                       const float* __restrict__ bm, const float* __restrict__ bu)
{
    int l = blockIdx.y;
    int r = blockIdx.x;          // 0..256
    int j = threadIdx.x;         // 128
    const float* WuL = Wu + (size_t)l * 2 * HH * HH;   // [256][128]
    if (r < HH) {
        g_Ws[((size_t)l * 256 + r) * HH + j] = __float2half(WuL[(size_t)r * HH + j]);
    } else if (r < 2 * HH) {
        int rr = r - HH;
        __shared__ float wm[HH];
        wm[j] = Wm[((size_t)l * HH + rr) * HH + j];
        __syncthreads();
        float acc = 0.f;
#pragma unroll 8
        for (int k = 0; k < HH; k++)
            acc += wm[k] * WuL[(size_t)(HH + k) * HH + j];
        g_Ws[((size_t)l * 256 + r) * HH + j] = __float2half(acc);
    } else {
        __shared__ float bb[HH];
        bb[j] = bm[l * HH + j];
        __syncthreads();
        float acc = bu[l * HH + j];
#pragma unroll 8
        for (int k = 0; k < HH; k++)
            acc += bb[k] * WuL[(size_t)(HH + k) * HH + j];
        g_bc[l * HH + j] = acc;
    }
}

// ---------------- comb[:,0:128] = h0_16 ----------------
__global__ void copy_h0()
{
    int i = blockIdx.x * 256 + threadIdx.x;
    if (i < NN * HH / 8) {
        int n = i >> 4;
        int c = (i & 15) * 8;
        *reinterpret_cast<float4*>(g_comb + (size_t)n * 256 + c) =
            *reinterpret_cast<const float4*>(g_h016 + (size_t)n * 128 + c);
    }
}

// -------- fp16 wmma GEMM, BM=32 (grid 256 -> good occupancy for small-K GEMMs) --------
__global__ __launch_bounds__(256) void gemm_k(
    const __half* __restrict__ A, int lda,
    const __half* __restrict__ B, int ldb,
    float* __restrict__ C32, int ldc32,
    __half* __restrict__ C16, int ldc16,
    const float* __restrict__ bias,
    int K, int relu)
{
    constexpr int BM = 32, BN = 128, BK = 64;
    __shared__ __align__(16) char sraw[22016];    // sA 32x72x2=4608, sB 64x136x2=17408
    __half (*sA)[BK + 8] = reinterpret_cast<__half(*)[BK + 8]>(sraw);
    __half (*sB)[BN + 8] = reinterpret_cast<__half(*)[BN + 8]>(sraw + 4608);
    float* sC = reinterpret_cast<float*>(sraw);   // 32x132 f32 = 16896 B

    int tid = threadIdx.x;
    int wid = tid >> 5;
    int bm = blockIdx.x * BM;
    int wm = (wid >> 2) * 16;
    int wn = (wid & 3) * 32;

    wmma::fragment<wmma::accumulator, 16, 16, 16, float> acc[2];
#pragma unroll
    for (int j = 0; j < 2; j++) wmma::fill_fragment(acc[j], 0.0f);

    float4 ra, rb[4];
    {
        int idx = tid * 8;
        ra = *reinterpret_cast<const float4*>(A + (size_t)(bm + (idx >> 6)) * lda + (idx & 63));
#pragma unroll
        for (int i = 0; i < 4; i++) {
            int bidx = tid * 8 + i * 2048;
            rb[i] = *reinterpret_cast<const float4*>(B + (size_t)(bidx >> 7) * ldb + (bidx & 127));
        }
    }

    int nk = K >> 6;
    for (int kt = 0; kt < nk; kt++) {
        {
            int idx = tid * 8;
            *reinterpret_cast<float4*>(&sA[idx >> 6][idx & 63]) = ra;
#pragma unroll
            for (int i = 0; i < 4; i++) {
                int bidx = tid * 8 + i * 2048;
                *reinterpret_cast<float4*>(&sB[bidx >> 7][bidx & 127]) = rb[i];
            }
        }
        __syncthreads();

        if (kt + 1 < nk) {
            int k0 = (kt + 1) << 6;
            int idx = tid * 8;
            ra = *reinterpret_cast<const float4*>(A + (size_t)(bm + (idx >> 6)) * lda + k0 + (idx & 63));
#pragma unroll
            for (int i = 0; i < 4; i++) {
                int bidx = tid * 8 + i * 2048;
                rb[i] = *reinterpret_cast<const float4*>(B + (size_t)(k0 + (bidx >> 7)) * ldb + (bidx & 127));
            }
        }

#pragma unroll
        for (int kk = 0; kk < BK; kk += 16) {
            wmma::fragment<wmma::matrix_a, 16, 16, 16, __half, wmma::row_major> fa;
            wmma::fragment<wmma::matrix_b, 16, 16, 16, __half, wmma::row_major> fb[2];
            wmma::load_matrix_sync(fa, &sA[wm][kk], BK + 8);
            wmma::load_matrix_sync(fb[0], &sB[kk][wn], BN + 8);
            wmma::load_matrix_sync(fb[1], &sB[kk][wn + 16], BN + 8);
#pragma unroll
            for (int j = 0; j < 2; j++)
                wmma::mma_sync(acc[j], fa, fb[j], acc[j]);
        }
        __syncthreads();
    }

#pragma unroll
    for (int j = 0; j < 2; j++)
        wmma::store_matrix_sync(sC + (size_t)wm * 132 + (wn + 16 * j),
                                acc[j], 132, wmma::mem_row_major);
    __syncthreads();

    for (int e = tid; e < BM * BN; e += 256) {
        int r = e >> 7, c = e & 127;
        float vv = sC[r * 132 + c];
        if (bias) vv += bias[c];
        if (relu) vv = fmaxf(vv, 0.0f);
        if (C16) C16[(size_t)(bm + r) * ldc16 + c] = __float2half(vv);
        if (C32) C32[(size_t)(bm + r) * ldc32 + c] = vv;
    }
}

// ---------------- attention over layers + output projection ----------------
__global__ __launch_bounds__(256) void attn_out(
    const float* __restrict__ Wa, const float* __restrict__ ba,
    const float* __restrict__ v, const float* __restrict__ Wo,
    const float* __restrict__ bo, float* __restrict__ out)
{
    __shared__ float sWa[HH * 4];
    __shared__ float sba[4], sv[4];
    __shared__ float smix[8][4][132];
    int t = threadIdx.x;
    for (int i = t; i < HH * 4; i += 256) sWa[i] = Wa[i];
    if (t < 4) { sba[t] = ba[t]; sv[t] = v[t]; }
    __syncthreads();

    int w = t >> 5, lane = t & 31;
    for (int q = 0; q < 4; q++) {
        int n = blockIdx.x * 32 + w * 4 + q;
        float e[3][4];
#pragma unroll
        for (int l = 0; l < 3; l++)
#pragma unroll
            for (int ii = 0; ii < 4; ii++)
                e[l][ii] = g_embs[((size_t)l * NN + n) * HH + lane + 32 * ii];

        float sc[3];
#pragma unroll
        for (int l = 0; l < 3; l++) {
            float s = 0.f;
#pragma unroll
            for (int hd = 0; hd < 4; hd++) {
                float d = 0.f;
#pragma unroll
                for (int ii = 0; ii < 4; ii++)
                    d += e[l][ii] * sWa[(lane + 32 * ii) * 4 + hd];
#pragma unroll
                for (int o = 16; o; o >>= 1) d += __shfl_xor_sync(0xFFFFFFFFu, d, o);
                s += tanhf(d + sba[hd]) * sv[hd];
            }
            sc[l] = s;
        }
        float mx = fmaxf(sc[0], fmaxf(sc[1], sc[2]));
        float w0 = expf(sc[0] - mx), w1 = expf(sc[1] - mx), w2 = expf(sc[2] - mx);
        float inv = 1.0f / (w0 + w1 + w2);
        w0 *= inv; w1 *= inv; w2 *= inv;
#pragma unroll
        for (int ii = 0; ii < 4; ii++)
            smix[w][q][lane + 32 * ii] = w0 * e[0][ii] + w1 * e[1][ii] + w2 * e[2][ii];
        __syncwarp();
#pragma unroll
        for (int jj = 0; jj < 4; jj++) {
            int j = lane + 32 * jj;
            float a = bo[j];
            for (int h = 0; h < HH; h++)
                a += smix[w][q][h] * Wo[h * HH + j];
            out[(size_t)n * HH + j] = a;
        }
        __syncwarp();
    }
}

// ---------------- deterministic mean reduction ----------------
__global__ void mean_part(const float* __restrict__ out)
{
    int b = blockIdx.x;
    int t = threadIdx.x;
    float s = 0.f;
    for (int r = 0; r < 64; r++)
        s += out[((size_t)b * 64 + r) * HH + t];
    g_part[b * HH + t] = s;
}
__global__ void mean_fin(float* __restrict__ gout)
{
    int t = threadIdx.x;
    float s = 0.f;
    for (int i = 0; i < 128; i++) s += g_part[i * HH + t];
    gout[t] = s * (1.0f / (float)NN);
}

// ---------------- launcher ----------------
extern "C" void kernel_launch(void* const* d_in, const int* in_sizes, int n_in,
                              void* d_out, int out_size)
{
    (void)in_sizes; (void)n_in; (void)out_size;
    const float* nf  = (const float*)d_in[0];
    const float* adj = (const float*)d_in[1];
    const float* bi  = (const float*)d_in[3];
    const float* Wa  = (const float*)d_in[8];
    const float* ba  = (const float*)d_in[9];
    const float* v   = (const float*)d_in[10];
    const float* Wo  = (const float*)d_in[11];
    const float* bo  = (const float*)d_in[12];
    float* out = (float*)d_out;

    __half *A16, *X16, *Wi16, *Ws, *h016, *comb;
    float *invdeg, *embs, *ps, *bc;
    cudaGetSymbolAddress((void**)&A16,   g_A16);
    cudaGetSymbolAddress((void**)&X16,   g_X16);
    cudaGetSymbolAddress((void**)&Wi16,  g_Wi16);
    cudaGetSymbolAddress((void**)&Ws,    g_Ws);
    cudaGetSymbolAddress((void**)&h016,  g_h016);
    cudaGetSymbolAddress((void**)&comb,  g_comb);
    cudaGetSymbolAddress((void**)&invdeg, g_invdeg);
    cudaGetSymbolAddress((void**)&embs,  g_embs);
    cudaGetSymbolAddress((void**)&ps,    g_ps);
    cudaGetSymbolAddress((void**)&bc,    g_bc);

    cudaFuncSetAttribute(gemm_big, cudaFuncAttributeMaxDynamicSharedMemorySize, GB_SMEM);

    // side stream + events for overlapping prep_adj(net+1) with net-k compute.
    cudaStream_t s = 0;
    if (cudaStreamCreateWithFlags(&s, cudaStreamNonBlocking) != cudaSuccess) s = 0;
    cudaEvent_t e0, eF[2], eP[3];
    cudaEventCreateWithFlags(&e0, cudaEventDisableTiming);
    for (int i = 0; i < 2; i++) cudaEventCreateWithFlags(&eF[i], cudaEventDisableTiming);
    for (int i = 0; i < 3; i++) cudaEventCreateWithFlags(&eP[i], cudaEventDisableTiming);

    // fork: prep net 0 into buffer 0 on side stream
    cudaEventRecord(e0, 0);
    cudaStreamWaitEvent(s, e0, 0);
    prep_adj<<<NN, 256, 0, s>>>(adj, A16, invdeg);
    cudaEventRecord(eP[0], s);

    // main: small prep work (overlaps prep_adj net 0)
    f2h<<<(NN * IND / 4 + 255) / 256, 256>>>(nf, X16, NN * IND / 4);
    f2h<<<(IND * HH / 4 + 255) / 256, 256>>>((const float*)d_in[2], Wi16, IND * HH / 4);
    fuse_w<<<dim3(2 * HH + 1, NL), HH>>>((const float*)d_in[4], (const float*)d_in[6],
                                          (const float*)d_in[5], (const float*)d_in[7]);
    gemm_k<<<256, 256>>>(X16, IND, Wi16, HH,
                         nullptr, 0, h016, HH, bi, IND, 0);

    // message passing; prep of net+1 overlaps net's compute chain (disjoint A16 buffer)
    for (int net = 0; net < NNET; net++) {
        int buf = net & 1;
        cudaStreamWaitEvent(0, eP[net], 0);          // A16[buf] ready
        if (net + 1 < NNET) {
            cudaEventRecord(eF[net & 1], 0);         // main done reading A16[buf^1]
            cudaStreamWaitEvent(s, eF[net & 1], 0);
            prep_adj<<<NN, 256, 0, s>>>(adj + (size_t)(net + 1) * NN * NN,
                                        A16 + (size_t)((net + 1) & 1) * NN * NN,
                                        invdeg + (net + 1) * NN);
            cudaEventRecord(eP[net + 1], s);
        }
        copy_h0<<<(NN * HH / 8 + 255) / 256, 256>>>();
        for (int l = 0; l < NL; l++) {
            const __half* Bsrc = (l == 0) ? h016 : comb;
            int ldb = (l == 0) ? HH : 2 * HH;
            gemm_big<<<dim3(NN / 128, 2), 256, GB_SMEM>>>(
                A16 + (size_t)buf * NN * NN, Bsrc, ldb, ps);
            combine_k<<<NN * HH / 4 / 256, 256>>>(invdeg + net * NN);
            float* c32 = (l == NL - 1) ? (embs + (size_t)net * NN * HH) : nullptr;
            gemm_k<<<256, 256>>>(comb, 2 * HH, Ws + (size_t)l * 2 * HH * HH, HH,
                                 c32, HH, comb, 2 * HH,
                                 bc + l * HH, 2 * HH, 1);
        }
    }

    // cross-layer attention + output projection
    attn_out<<<NN / 32, 256>>>(Wa, ba, v, Wo, bo, out);

    // deterministic mean over nodes
    mean_part<<<128, 128>>>(out);
    mean_fin<<<1, 128>>>(out + (size_t)NN * HH);
}

// round 16
// speedup vs baseline: 1.1212x; 1.0563x over previous
#include <cuda_runtime.h>
#include <cuda_fp16.h>
#include <mma.h>
#include <cstdint>
#include <cstddef>

using namespace nvcuda;

#define NN    8192
#define IND   256
#define HH    128
#define NL    3
#define NNET  3

// ---------------- device scratch (static, allowed) ----------------
__device__ __align__(16) __half g_A16[2][(size_t)NN * NN];       // double-buffered fp16 adj (2x134 MB)
__device__ __align__(16) __half g_X16[NN * IND];
__device__ __align__(16) __half g_Wi16[IND * HH];
__device__ __align__(16) __half g_Ws[NL * 2 * HH * HH];          // fused [Wu_top; Wm@Wu_bot]
__device__ float g_bc[NL * HH];                                   // fused bias
__device__ __align__(16) __half g_h016[NN * HH];
__device__ __align__(16) __half g_h[NN * HH];                    // current h (dense, ldb=128)
__device__ __align__(16) float g_ps[2 * NN * HH];                // split-K fp32 partials
__device__ float g_invdeg[NNET * NN];                             // per-net 1/deg
__device__ float g_embs[(size_t)NNET * NN * HH];                 // per-net final layer embeddings
__device__ float g_part[128 * HH];

// ---------------- helpers ----------------
__device__ __forceinline__ uint32_t s2u(const void* p){
    uint32_t a;
    asm("{ .reg .u64 t; cvta.to.shared.u64 t, %1; cvt.u32.u64 %0, t; }" : "=r"(a) : "l"(p));
    return a;
}
__device__ __forceinline__ void cp16(uint32_t dst, const void* src){
    asm volatile("cp.async.cg.shared.global [%0], [%1], 16;" :: "r"(dst), "l"(src));
}
#define CP_COMMIT() asm volatile("cp.async.commit_group;" ::: "memory")
#define CP_WAIT2()  asm volatile("cp.async.wait_group 2;" ::: "memory")

// =================== pipelined SpMM: part = A16 @ B (fp32 partials) ===================
// grid (64, 2). BM=128, BK=64, 6 stages, occ-1, TWO stages per barrier (round-15 best).
#define GB_S    6
#define GB_ASZ  (128 * 72 * 2)                  // 18432 B
#define GB_BSZ  (64 * 136 * 2)                  // 17408 B
#define GB_STG  (GB_ASZ + GB_BSZ)               // 35840 B
#define GB_SMEM (GB_S * GB_STG)                 // 215040 B

__global__ __launch_bounds__(256, 1) void gemm_big(
    const __half* __restrict__ A,
    const __half* __restrict__ B, int ldb,
    float* __restrict__ part)
{
    extern __shared__ char dsm[];
    uint32_t sb = s2u(dsm);
    int tid = threadIdx.x;
    int wid = tid >> 5;
    int bm = blockIdx.x * 128;
    int kbase = blockIdx.y * 4096;
    int wm = (wid >> 1) * 32;
    int wn = (wid & 1) * 64;

    auto load_stage = [&](int st, int kt) {
        int k0 = kbase + kt * 64;
        uint32_t abase = sb + st * GB_STG;
        uint32_t bbase = abase + GB_ASZ;
#pragma unroll
        for (int i = 0; i < 4; i++) {
            int idx = tid + i * 256;
            int r = idx >> 3, c = idx & 7;
            cp16(abase + r * 144 + c * 16,
                 A + (size_t)(bm + r) * NN + k0 + c * 8);
        }
#pragma unroll
        for (int i = 0; i < 4; i++) {
            int idx = tid + i * 256;
            int r = idx >> 4, c = idx & 15;
            cp16(bbase + r * 272 + c * 16,
                 B + (size_t)(k0 + r) * ldb + c * 8);
        }
    };

    auto mma_stage = [&](int st,
                         wmma::fragment<wmma::accumulator, 16, 16, 16, float> (&acc)[2][4]) {
        const __half* pA = reinterpret_cast<const __half*>(dsm + st * GB_STG);
        const __half* pB = reinterpret_cast<const __half*>(dsm + st * GB_STG + GB_ASZ);
#pragma unroll
        for (int kk = 0; kk < 64; kk += 16) {
            wmma::fragment<wmma::matrix_a, 16, 16, 16, __half, wmma::row_major> fa[2];
            wmma::fragment<wmma::matrix_b, 16, 16, 16, __half, wmma::row_major> fb[4];
#pragma unroll
            for (int i = 0; i < 2; i++)
                wmma::load_matrix_sync(fa[i], pA + (size_t)(wm + 16 * i) * 72 + kk, 72);
#pragma unroll
            for (int j = 0; j < 4; j++)
                wmma::load_matrix_sync(fb[j], pB + (size_t)kk * 136 + wn + 16 * j, 136);
#pragma unroll
            for (int i = 0; i < 2; i++)
#pragma unroll
                for (int j = 0; j < 4; j++)
                    wmma::mma_sync(acc[i][j], fa[i], fb[j], acc[i][j]);
        }
    };

    wmma::fragment<wmma::accumulator, 16, 16, 16, float> acc[2][4];
#pragma unroll
    for (int i = 0; i < 2; i++)
#pragma unroll
        for (int j = 0; j < 4; j++)
            wmma::fill_fragment(acc[i][j], 0.0f);

#pragma unroll
    for (int s = 0; s < 4; s++) { load_stage(s, s); CP_COMMIT(); }

    const int nk = 4096 / 64;
    int st_use = 0, st_load = 4;
    for (int kt = 0; kt < nk; kt += 2) {
        CP_WAIT2();
        __syncthreads();

        if (kt + 4 < nk) load_stage(st_load, kt + 4);
        CP_COMMIT();
        int st_load2 = (st_load + 1 == GB_S) ? 0 : st_load + 1;
        if (kt + 5 < nk) load_stage(st_load2, kt + 5);
        CP_COMMIT();

        mma_stage(st_use, acc);
        int st_use2 = (st_use + 1 == GB_S) ? 0 : st_use + 1;
        mma_stage(st_use2, acc);

        st_use = (st_use + 2 >= GB_S) ? st_use + 2 - GB_S : st_use + 2;
        st_load = (st_load + 2 >= GB_S) ? st_load + 2 - GB_S : st_load + 2;
    }

    __syncthreads();
    float* sC = reinterpret_cast<float*>(dsm);     // 128 x 132 overlays stage memory
#pragma unroll
    for (int i = 0; i < 2; i++)
#pragma unroll
        for (int j = 0; j < 4; j++)
            wmma::store_matrix_sync(sC + (size_t)(wm + 16 * i) * 132 + wn + 16 * j,
                                    acc[i][j], 132, wmma::mem_row_major);
    __syncthreads();

    float* out = part + (size_t)blockIdx.y * NN * HH + (size_t)bm * HH;
    for (int e = tid; e < 128 * 128 / 4; e += 256) {
        int r = e >> 5, c = (e & 31) * 4;
        *reinterpret_cast<float4*>(out + (size_t)r * HH + c) =
            *reinterpret_cast<const float4*>(sC + (size_t)r * 132 + c);
    }
}

// ====== fused update GEMM: h_new = relu([h | (ps0+ps1)*inv] @ Ws + bc) ======
// BM=32, K=256 whole operands staged once; single pre-MMA barrier; occ 2.
// A msg-half is assembled from split-K partials during staging (replaces combine_k).
#define GU_ASZ  (32 * 264 * 2)                  // 16896 B (sA, 256+8 pad)
#define GU_BSZ  (256 * 136 * 2)                 // 69632 B (sB, 128+8 pad)
#define GU_SMEM (GU_ASZ + GU_BSZ)               // 86528 B

__global__ __launch_bounds__(256, 2) void gemm_upd(
    const __half* __restrict__ hsrc,            // current h [NN x 128]
    const float* __restrict__ inv,              // 1/deg for this net
    const __half* __restrict__ W,               // Ws[l] [256 x 128]
    float* __restrict__ C32,                    // optional fp32 embs out
    const float* __restrict__ bias)             // bc[l]
{
    extern __shared__ char dsm[];
    __half (*sA)[264] = reinterpret_cast<__half(*)[264]>(dsm);
    __half (*sB)[136] = reinterpret_cast<__half(*)[136]>(dsm + GU_ASZ);
    float* sC = reinterpret_cast<float*>(dsm);  // 32x132 overlay (16896 B, fits sA)

    int tid = threadIdx.x;
    int wid = tid >> 5;
    int bm = blockIdx.x * 32;

    // ---- stage A h-half: 32x128 fp16 (16 halves/thread) ----
    {
        int idx = tid * 16;                     // 0..4095
        int r = idx >> 7, c = idx & 127;
        const float4* src = reinterpret_cast<const float4*>(hsrc + (size_t)(bm + r) * HH + c);
        *reinterpret_cast<float4*>(&sA[r][c])     = src[0];
        *reinterpret_cast<float4*>(&sA[r][c + 8]) = src[1];
    }
    // ---- stage A msg-half: (ps0+ps1)*inv -> fp16 (identical math to combine_k) ----
    {
        int idx = tid * 16;
        int r = idx >> 7, c = idx & 127;
        float s = inv[bm + r];
        const float* p0 = g_ps + (size_t)(bm + r) * HH + c;
        const float* p1 = p0 + (size_t)NN * HH;
#pragma unroll
        for (int j = 0; j < 4; j++) {
            float4 a = *reinterpret_cast<const float4*>(p0 + j * 4);
            float4 b = *reinterpret_cast<const float4*>(p1 + j * 4);
            __half2 h0 = __floats2half2_rn((a.x + b.x) * s, (a.y + b.y) * s);
            __half2 h1 = __floats2half2_rn((a.z + b.z) * s, (a.w + b.w) * s);
            uint2 u;
            u.x = *reinterpret_cast<unsigned*>(&h0);
            u.y = *reinterpret_cast<unsigned*>(&h1);
            *reinterpret_cast<uint2*>(&sA[r][128 + c + j * 4]) = u;
        }
    }
    // ---- stage B: full Ws[l] 256x128 (128 halves/thread) ----
#pragma unroll
    for (int i = 0; i < 16; i++) {
        int idx = tid * 8 + i * 2048;
        int r = idx >> 7, c = idx & 127;
        *reinterpret_cast<float4*>(&sB[r][c]) =
            *reinterpret_cast<const float4*>(W + (size_t)r * HH + c);
    }
    __syncthreads();

    // ---- MMA: warp tile 16x32, 16 straight kk steps, no mainloop barriers ----
    int wm = (wid >> 2) * 16;
    int wn = (wid & 3) * 32;
    wmma::fragment<wmma::accumulator, 16, 16, 16, float> acc[2];
#pragma unroll
    for (int j = 0; j < 2; j++) wmma::fill_fragment(acc[j], 0.0f);
#pragma unroll
    for (int kk = 0; kk < 256; kk += 16) {
        wmma::fragment<wmma::matrix_a, 16, 16, 16, __half, wmma::row_major> fa;
        wmma::fragment<wmma::matrix_b, 16, 16, 16, __half, wmma::row_major> fb[2];
        wmma::load_matrix_sync(fa, &sA[wm][kk], 264);
        wmma::load_matrix_sync(fb[0], &sB[kk][wn], 136);
        wmma::load_matrix_sync(fb[1], &sB[kk][wn + 16], 136);
#pragma unroll
        for (int j = 0; j < 2; j++)
            wmma::mma_sync(acc[j], fa, fb[j], acc[j]);
    }
    __syncthreads();

#pragma unroll
    for (int j = 0; j < 2; j++)
        wmma::store_matrix_sync(sC + (size_t)wm * 132 + wn + 16 * j,
                                acc[j], 132, wmma::mem_row_major);
    __syncthreads();

    for (int e = tid; e < 32 * 128; e += 256) {
        int r = e >> 7, c = e & 127;
        float vv = fmaxf(sC[r * 132 + c] + bias[c], 0.0f);
        g_h[(size_t)(bm + r) * HH + c] = __float2half(vv);
        if (C32) C32[(size_t)(bm + r) * HH + c] = vv;
    }
}

// ---------------- adj fp32 -> fp16 + row-sum (one pass, pure-BW) ----------------
__global__ void prep_adj(const float* __restrict__ src0,
                         __half* __restrict__ dst0,
                         float* __restrict__ invdeg)
{
    size_t row = blockIdx.x;
    const float* src = src0 + row * NN;
    __half* dst = dst0 + row * NN;
    int t = threadIdx.x;
    float s = 0.f;
#pragma unroll
    for (int i = 0; i < 8; i++) {
        int v4 = t + i * 256;
        float4 f = *reinterpret_cast<const float4*>(src + (size_t)v4 * 4);
        s += f.x + f.y + f.z + f.w;
        __half2 h0 = __floats2half2_rn(f.x, f.y);
        __half2 h1 = __floats2half2_rn(f.z, f.w);
        uint2 u;
        u.x = *reinterpret_cast<unsigned*>(&h0);
        u.y = *reinterpret_cast<unsigned*>(&h1);
        *reinterpret_cast<uint2*>(dst + (size_t)v4 * 4) = u;
    }
#pragma unroll
    for (int o = 16; o; o >>= 1) s += __shfl_xor_sync(0xFFFFFFFFu, s, o);
    __shared__ float ws[8];
    int wid = t >> 5, lane = t & 31;
    if (lane == 0) ws[wid] = s;
    __syncthreads();
    if (t == 0) {
        float tot = 0.f;
#pragma unroll
        for (int i = 0; i < 8; i++) tot += ws[i];
        invdeg[row] = 1.0f / fmaxf(tot, 1.0f);
    }
}

// ---------------- generic fp32 -> fp16 convert ----------------
__global__ void f2h(const float* __restrict__ src, __half* __restrict__ dst, int n4)
{
    int i = blockIdx.x * blockDim.x + threadIdx.x;
    if (i < n4) {
        float4 f = reinterpret_cast<const float4*>(src)[i];
        __half2 a = __floats2half2_rn(f.x, f.y);
        __half2 b = __floats2half2_rn(f.z, f.w);
        uint2 u;
        u.x = *reinterpret_cast<unsigned*>(&a);
        u.y = *reinterpret_cast<unsigned*>(&b);
        *reinterpret_cast<uint2*>(dst + (size_t)i * 4) = u;
    }
}

// ------- fused weight precompute: Ws[l] = [Wu_top ; Wm[l]@Wu_bot], bc[l] = bm@Wu_bot + bu -------
__global__ void fuse_w(const float* __restrict__ Wm, const float* __restrict__ Wu,
                       const float* __restrict__ bm, const float* __restrict__ bu)
{
    int l = blockIdx.y;
    int r = blockIdx.x;          // 0..256
    int j = threadIdx.x;         // 128
    const float* WuL = Wu + (size_t)l * 2 * HH * HH;   // [256][128]
    if (r < HH) {
        g_Ws[((size_t)l * 256 + r) * HH + j] = __float2half(WuL[(size_t)r * HH + j]);
    } else if (r < 2 * HH) {
        int rr = r - HH;
        __shared__ float wm[HH];
        wm[j] = Wm[((size_t)l * HH + rr) * HH + j];
        __syncthreads();
        float acc = 0.f;
#pragma unroll 8
        for (int k = 0; k < HH; k++)
            acc += wm[k] * WuL[(size_t)(HH + k) * HH + j];
        g_Ws[((size_t)l * 256 + r) * HH + j] = __float2half(acc);
    } else {
        __shared__ float bb[HH];
        bb[j] = bm[l * HH + j];
        __syncthreads();
        float acc = bu[l * HH + j];
#pragma unroll 8
        for (int k = 0; k < HH; k++)
            acc += bb[k] * WuL[(size_t)(HH + k) * HH + j];
        g_bc[l * HH + j] = acc;
    }
}

// -------- fp16 wmma GEMM, BM=32 (h0 projection only) --------
__global__ __launch_bounds__(256) void gemm_k(
    const __half* __restrict__ A, int lda,
    const __half* __restrict__ B, int ldb,
    float* __restrict__ C32, int ldc32,
    __half* __restrict__ C16, int ldc16,
    const float* __restrict__ bias,
    int K, int relu)
{
    constexpr int BM = 32, BN = 128, BK = 64;
    __shared__ __align__(16) char sraw[22016];
    __half (*sA)[BK + 8] = reinterpret_cast<__half(*)[BK + 8]>(sraw);
    __half (*sB)[BN + 8] = reinterpret_cast<__half(*)[BN + 8]>(sraw + 4608);
    float* sC = reinterpret_cast<float*>(sraw);

    int tid = threadIdx.x;
    int wid = tid >> 5;
    int bm = blockIdx.x * BM;
    int wm = (wid >> 2) * 16;
    int wn = (wid & 3) * 32;

    wmma::fragment<wmma::accumulator, 16, 16, 16, float> acc[2];
#pragma unroll
    for (int j = 0; j < 2; j++) wmma::fill_fragment(acc[j], 0.0f);

    float4 ra, rb[4];
    {
        int idx = tid * 8;
        ra = *reinterpret_cast<const float4*>(A + (size_t)(bm + (idx >> 6)) * lda + (idx & 63));
#pragma unroll
        for (int i = 0; i < 4; i++) {
            int bidx = tid * 8 + i * 2048;
            rb[i] = *reinterpret_cast<const float4*>(B + (size_t)(bidx >> 7) * ldb + (bidx & 127));
        }
    }

    int nk = K >> 6;
    for (int kt = 0; kt < nk; kt++) {
        {
            int idx = tid * 8;
            *reinterpret_cast<float4*>(&sA[idx >> 6][idx & 63]) = ra;
#pragma unroll
            for (int i = 0; i < 4; i++) {
                int bidx = tid * 8 + i * 2048;
                *reinterpret_cast<float4*>(&sB[bidx >> 7][bidx & 127]) = rb[i];
            }
        }
        __syncthreads();

        if (kt + 1 < nk) {
            int k0 = (kt + 1) << 6;
            int idx = tid * 8;
            ra = *reinterpret_cast<const float4*>(A + (size_t)(bm + (idx >> 6)) * lda + k0 + (idx & 63));
#pragma unroll
            for (int i = 0; i < 4; i++) {
                int bidx = tid * 8 + i * 2048;
                rb[i] = *reinterpret_cast<const float4*>(B + (size_t)(k0 + (bidx >> 7)) * ldb + (bidx & 127));
            }
        }

#pragma unroll
        for (int kk = 0; kk < BK; kk += 16) {
            wmma::fragment<wmma::matrix_a, 16, 16, 16, __half, wmma::row_major> fa;
            wmma::fragment<wmma::matrix_b, 16, 16, 16, __half, wmma::row_major> fb[2];
            wmma::load_matrix_sync(fa, &sA[wm][kk], BK + 8);
            wmma::load_matrix_sync(fb[0], &sB[kk][wn], BN + 8);
            wmma::load_matrix_sync(fb[1], &sB[kk][wn + 16], BN + 8);
#pragma unroll
            for (int j = 0; j < 2; j++)
                wmma::mma_sync(acc[j], fa, fb[j], acc[j]);
        }
        __syncthreads();
    }

#pragma unroll
    for (int j = 0; j < 2; j++)
        wmma::store_matrix_sync(sC + (size_t)wm * 132 + (wn + 16 * j),
                                acc[j], 132, wmma::mem_row_major);
    __syncthreads();

    for (int e = tid; e < BM * BN; e += 256) {
        int r = e >> 7, c = e & 127;
        float vv = sC[r * 132 + c];
        if (bias) vv += bias[c];
        if (relu) vv = fmaxf(vv, 0.0f);
        if (C16) C16[(size_t)(bm + r) * ldc16 + c] = __float2half(vv);
        if (C32) C32[(size_t)(bm + r) * ldc32 + c] = vv;
    }
}

// ---------------- attention over layers + output projection ----------------
__global__ __launch_bounds__(256) void attn_out(
    const float* __restrict__ Wa, const float* __restrict__ ba,
    const float* __restrict__ v, const float* __restrict__ Wo,
    const float* __restrict__ bo, float* __restrict__ out)
{
    __shared__ float sWa[HH * 4];
    __shared__ float sba[4], sv[4];
    __shared__ float smix[8][4][132];
    int t = threadIdx.x;
    for (int i = t; i < HH * 4; i += 256) sWa[i] = Wa[i];
    if (t < 4) { sba[t] = ba[t]; sv[t] = v[t]; }
    __syncthreads();

    int w = t >> 5, lane = t & 31;
    for (int q = 0; q < 4; q++) {
        int n = blockIdx.x * 32 + w * 4 + q;
        float e[3][4];
#pragma unroll
        for (int l = 0; l < 3; l++)
#pragma unroll
            for (int ii = 0; ii < 4; ii++)
                e[l][ii] = g_embs[((size_t)l * NN + n) * HH + lane + 32 * ii];

        float sc[3];
#pragma unroll
        for (int l = 0; l < 3; l++) {
            float s = 0.f;
#pragma unroll
            for (int hd = 0; hd < 4; hd++) {
                float d = 0.f;
#pragma unroll
                for (int ii = 0; ii < 4; ii++)
                    d += e[l][ii] * sWa[(lane + 32 * ii) * 4 + hd];
#pragma unroll
                for (int o = 16; o; o >>= 1) d += __shfl_xor_sync(0xFFFFFFFFu, d, o);
                s += tanhf(d + sba[hd]) * sv[hd];
            }
            sc[l] = s;
        }
        float mx = fmaxf(sc[0], fmaxf(sc[1], sc[2]));
        float w0 = expf(sc[0] - mx), w1 = expf(sc[1] - mx), w2 = expf(sc[2] - mx);
        float inv = 1.0f / (w0 + w1 + w2);
        w0 *= inv; w1 *= inv; w2 *= inv;
#pragma unroll
        for (int ii = 0; ii < 4; ii++)
            smix[w][q][lane + 32 * ii] = w0 * e[0][ii] + w1 * e[1][ii] + w2 * e[2][ii];
        __syncwarp();
#pragma unroll
        for (int jj = 0; jj < 4; jj++) {
            int j = lane + 32 * jj;
            float a = bo[j];
            for (int h = 0; h < HH; h++)
                a += smix[w][q][h] * Wo[h * HH + j];
            out[(size_t)n * HH + j] = a;
        }
        __syncwarp();
    }
}

// ---------------- deterministic mean reduction ----------------
__global__ void mean_part(const float* __restrict__ out)
{
    int b = blockIdx.x;
    int t = threadIdx.x;
    float s = 0.f;
    for (int r = 0; r < 64; r++)
        s += out[((size_t)b * 64 + r) * HH + t];
    g_part[b * HH + t] = s;
}
__global__ void mean_fin(float* __restrict__ gout)
{
    int t = threadIdx.x;
    float s = 0.f;
    for (int i = 0; i < 128; i++) s += g_part[i * HH + t];
    gout[t] = s * (1.0f / (float)NN);
}

// ---------------- launcher ----------------
extern "C" void kernel_launch(void* const* d_in, const int* in_sizes, int n_in,
                              void* d_out, int out_size)
{
    (void)in_sizes; (void)n_in; (void)out_size;
    const float* nf  = (const float*)d_in[0];
    const float* adj = (const float*)d_in[1];
    const float* bi  = (const float*)d_in[3];
    const float* Wa  = (const float*)d_in[8];
    const float* ba  = (const float*)d_in[9];
    const float* v   = (const float*)d_in[10];
    const float* Wo  = (const float*)d_in[11];
    const float* bo  = (const float*)d_in[12];
    float* out = (float*)d_out;

    __half *A16, *X16, *Wi16, *Ws, *h016, *hcur;
    float *invdeg, *embs, *ps, *bc;
    cudaGetSymbolAddress((void**)&A16,   g_A16);
    cudaGetSymbolAddress((void**)&X16,   g_X16);
    cudaGetSymbolAddress((void**)&Wi16,  g_Wi16);
    cudaGetSymbolAddress((void**)&Ws,    g_Ws);
    cudaGetSymbolAddress((void**)&h016,  g_h016);
    cudaGetSymbolAddress((void**)&hcur,  g_h);
    cudaGetSymbolAddress((void**)&invdeg, g_invdeg);
    cudaGetSymbolAddress((void**)&embs,  g_embs);
    cudaGetSymbolAddress((void**)&ps,    g_ps);
    cudaGetSymbolAddress((void**)&bc,    g_bc);

    cudaFuncSetAttribute(gemm_big, cudaFuncAttributeMaxDynamicSharedMemorySize, GB_SMEM);
    cudaFuncSetAttribute(gemm_upd, cudaFuncAttributeMaxDynamicSharedMemorySize, GU_SMEM);

    // side stream + events for overlapping prep_adj(net+1) with net-k compute.
    cudaStream_t s = 0;
    if (cudaStreamCreateWithFlags(&s, cudaStreamNonBlocking) != cudaSuccess) s = 0;
    cudaEvent_t e0, eF[2], eP[3];
    cudaEventCreateWithFlags(&e0, cudaEventDisableTiming);
    for (int i = 0; i < 2; i++) cudaEventCreateWithFlags(&eF[i], cudaEventDisableTiming);
    for (int i = 0; i < 3; i++) cudaEventCreateWithFlags(&eP[i], cudaEventDisableTiming);

    // fork: prep net 0 into buffer 0 on side stream
    cudaEventRecord(e0, 0);
    cudaStreamWaitEvent(s, e0, 0);
    prep_adj<<<NN, 256, 0, s>>>(adj, A16, invdeg);
    cudaEventRecord(eP[0], s);

    // main: small prep work (overlaps prep_adj net 0)
    f2h<<<(NN * IND / 4 + 255) / 256, 256>>>(nf, X16, NN * IND / 4);
    f2h<<<(IND * HH / 4 + 255) / 256, 256>>>((const float*)d_in[2], Wi16, IND * HH / 4);
    fuse_w<<<dim3(2 * HH + 1, NL), HH>>>((const float*)d_in[4], (const float*)d_in[6],
                                          (const float*)d_in[5], (const float*)d_in[7]);
    gemm_k<<<256, 256>>>(X16, IND, Wi16, HH,
                         nullptr, 0, h016, HH, bi, IND, 0);

    // message passing; prep of net+1 overlaps net's compute chain (disjoint A16 buffer)
    for (int net = 0; net < NNET; net++) {
        int buf = net & 1;
        cudaStreamWaitEvent(0, eP[net], 0);          // A16[buf] ready
        if (net + 1 < NNET) {
            cudaEventRecord(eF[net & 1], 0);         // main done reading A16[buf^1]
            cudaStreamWaitEvent(s, eF[net & 1], 0);
            prep_adj<<<NN, 256, 0, s>>>(adj + (size_t)(net + 1) * NN * NN,
                                        A16 + (size_t)((net + 1) & 1) * NN * NN,
                                        invdeg + (net + 1) * NN);
            cudaEventRecord(eP[net + 1], s);
        }
        for (int l = 0; l < NL; l++) {
            const __half* hsrc = (l == 0) ? h016 : hcur;
            // partials = A[net] @ h  (fp32, two K-halves)
            gemm_big<<<dim3(NN / 128, 2), 256, GB_SMEM>>>(
                A16 + (size_t)buf * NN * NN, hsrc, HH, ps);
            // h = relu([h | (p0+p1)*inv] @ Ws[l] + bc[l])  (combine fused into staging)
            float* c32 = (l == NL - 1) ? (embs + (size_t)net * NN * HH) : nullptr;
            gemm_upd<<<NN / 32, 256, GU_SMEM>>>(hsrc, invdeg + net * NN,
                                                Ws + (size_t)l * 2 * HH * HH,
                                                c32, bc + l * HH);
        }
    }

    // cross-layer attention + output projection
    attn_out<<<NN / 32, 256>>>(Wa, ba, v, Wo, bo, out);

    // deterministic mean over nodes
    mean_part<<<128, 128>>>(out);
    mean_fin<<<1, 128>>>(out + (size_t)NN * HH);
}